// round 10
// baseline (speedup 1.0000x reference)
#include <cuda_runtime.h>
#include <cuda_bf16.h>
#include <mma.h>
#include <cstdint>

using namespace nvcuda;

// ---------------- problem constants ----------------
#define NB 8            // batch
#define HW 384
#define CIN 3
#define PATCH 16
#define GRID 24         // 384/16
#define L 576           // GRID*GRID tokens
#define W 768           // width
#define DPT 4           // depth
#define NH 12           // heads
#define HD 64           // head dim
#define MLP 3072
#define M_ROWS (NB*L)   // 4608

// weight scratch layout (floats)
#define CONV_SZ (PATCH*PATCH*CIN*W)        // 589824
#define WQKV_SZ (W*W)                      // 589824
#define W1_SZ   (W*MLP)                    // 2359296
#define LAYER_SZ (4*WQKV_SZ + 2*W1_SZ)     // 7077888
#define WT_TOTAL (CONV_SZ + DPT*LAYER_SZ)  // 28901376

// ---------------- scratch (device globals; no allocation allowed) ----------
__device__ float g_x[M_ROWS * W];     // residual stream
__device__ float g_y[M_ROWS * W];     // LN output / im2col buffer
__device__ float g_q[M_ROWS * W];
__device__ float g_k[M_ROWS * W];
__device__ float g_v[M_ROWS * W];
__device__ float g_o[M_ROWS * W];
__device__ float g_h[M_ROWS * MLP];   // MLP hidden
__device__ float g_att[(size_t)NB * NH * L * L];  // attention scores/probs
__device__ float g_wt[WT_TOTAL];      // tf32-rounded weights
__device__ float g_rope[4][L][16];    // cosx,sinx,cosy,siny

// ---------------- helpers ----------------
__device__ __forceinline__ float gelu_tanh(float x) {
    const float k0 = 0.7978845608028654f;   // sqrt(2/pi)
    float x3 = x * x * x;
    return 0.5f * x * (1.0f + tanhf(k0 * (x + 0.044715f * x3)));
}

__device__ __forceinline__ void cp16(void* smem_dst, const void* gsrc) {
    uint32_t s = (uint32_t)__cvta_generic_to_shared(smem_dst);
    asm volatile("cp.async.cg.shared.global [%0], [%1], 16;\n" :: "r"(s), "l"(gsrc));
}
__device__ __forceinline__ void cp_commit() {
    asm volatile("cp.async.commit_group;\n" ::);
}
template <int N>
__device__ __forceinline__ void cp_wait() {
    asm volatile("cp.async.wait_group %0;\n" :: "n"(N));
}

// ---------------- weight tf32 pre-rounding ----------------
struct CvtJob { const float* src; float* dst; int n4; };
struct CvtJobs { CvtJob j[25]; };

__global__ void cvt_weights_kernel(CvtJobs jobs) {
    CvtJob jb = jobs.j[blockIdx.y];
    const float4* s = (const float4*)jb.src;
    float4* d = (float4*)jb.dst;
    for (int i = blockIdx.x * blockDim.x + threadIdx.x; i < jb.n4;
         i += gridDim.x * blockDim.x) {
        float4 t = s[i];
        t.x = wmma::__float_to_tf32(t.x);
        t.y = wmma::__float_to_tf32(t.y);
        t.z = wmma::__float_to_tf32(t.z);
        t.w = wmma::__float_to_tf32(t.w);
        d[i] = t;
    }
}

// ---------------- im2col: image(NHWC) -> rows [NB*L, 768], tf32-rounded ----
__global__ void im2col_kernel(const float* __restrict__ img, float* __restrict__ out) {
    int idx = blockIdx.x * blockDim.x + threadIdx.x;
    const int total = M_ROWS * W;
    if (idx >= total) return;
    int col = idx % W;
    int rest = idx / W;
    int p = rest % L;
    int n = rest / L;
    int c = col % CIN;
    int ij = col / CIN;
    int j = ij % PATCH;
    int i = ij / PATCH;
    int px = p % GRID, py = p / GRID;
    out[idx] = wmma::__float_to_tf32(
        img[(((size_t)n * HW + (py * PATCH + i)) * HW + (px * PATCH + j)) * CIN + c]);
}

// ---------------- RoPE cache ----------------
__global__ void rope_cache_kernel() {
    int idx = blockIdx.x * blockDim.x + threadIdx.x;
    if (idx >= L * 16) return;
    int l = idx / 16, f = idx % 16;
    int px = l % GRID, py = l / GRID;
    float u = (px + 0.5f) / (float)GRID;
    float v = (py + 0.5f) / (float)GRID;
    float fr = (float)f / (15.0f + 1e-9f);
    float inv = expf(-fr * 9.210340371976184f);  // 10000^-fr
    float ax = u * inv, ay = v * inv;
    g_rope[0][l][f] = cosf(ax);
    g_rope[1][l][f] = sinf(ax);
    g_rope[2][l][f] = cosf(ay);
    g_rope[3][l][f] = sinf(ay);
}

// ---------------- RoPE apply (in place on q or k) ----------------
__global__ void rope_apply_kernel(float* __restrict__ t) {
    int idx = blockIdx.x * blockDim.x + threadIdx.x;
    const int total = NB * L * NH * 32;   // 32 pairs per head
    if (idx >= total) return;
    int pair = idx & 31;
    int rest = idx >> 5;
    int h = rest % NH; rest /= NH;
    int l = rest % L;
    int n = rest / L;
    int f = pair & 15;
    float c, s;
    if (pair < 16) { c = g_rope[0][l][f]; s = g_rope[1][l][f]; }
    else           { c = g_rope[2][l][f]; s = g_rope[3][l][f]; }
    size_t base = ((((size_t)n * L + l) * NH + h) * HD) + pair * 2;
    float x = t[base], y = t[base + 1];
    t[base]     = x * c - y * s;
    t[base + 1] = x * s + y * c;
}

// ---------------- LayerNorm: warp per row, C = 768 fixed ----------------
// do_cvt=1: round output to tf32 (feeds a GEMM A operand)
__global__ void ln_warp(const float* __restrict__ x, const float* __restrict__ sc,
                        const float* __restrict__ bi, float* __restrict__ y,
                        int do_cvt) {
    int wid = threadIdx.x >> 5, lane = threadIdx.x & 31;
    int row = blockIdx.x * 8 + wid;
    const float4* xr = (const float4*)(x + (size_t)row * W);
    float4 v[6];
    float s1 = 0.f, s2 = 0.f;
    #pragma unroll
    for (int i = 0; i < 6; i++) {
        v[i] = xr[lane + 32 * i];
        s1 += v[i].x + v[i].y + v[i].z + v[i].w;
        s2 += v[i].x * v[i].x + v[i].y * v[i].y + v[i].z * v[i].z + v[i].w * v[i].w;
    }
    #pragma unroll
    for (int o = 16; o > 0; o >>= 1) {
        s1 += __shfl_xor_sync(0xffffffffu, s1, o);
        s2 += __shfl_xor_sync(0xffffffffu, s2, o);
    }
    float mean = s1 * (1.0f / W);
    float var  = s2 * (1.0f / W) - mean * mean;
    float rstd = rsqrtf(var + 1e-6f);
    float4* yr = (float4*)(y + (size_t)row * W);
    const float4* s4 = (const float4*)sc;
    const float4* b4 = (const float4*)bi;
    #pragma unroll
    for (int i = 0; i < 6; i++) {
        int idx = lane + 32 * i;
        float4 sv = s4[idx], bv = b4[idx], o;
        o.x = (v[i].x - mean) * rstd * sv.x + bv.x;
        o.y = (v[i].y - mean) * rstd * sv.y + bv.y;
        o.z = (v[i].z - mean) * rstd * sv.z + bv.z;
        o.w = (v[i].w - mean) * rstd * sv.w + bv.w;
        if (do_cvt) {
            o.x = wmma::__float_to_tf32(o.x);
            o.y = wmma::__float_to_tf32(o.y);
            o.z = wmma::__float_to_tf32(o.z);
            o.w = wmma::__float_to_tf32(o.w);
        }
        yr[idx] = o;
    }
}

// ---------------- tensor-core tf32 GEMM, cp.async 2-stage pipeline ----------
// Inputs A and B must already be tf32-rounded (producers handle this).
// C[M,N] = A[M,K] @ B[K,N] + bias[N]   (MODE 0)
//          gelu(...) [tf32-rounded]    (MODE 1)
//          ... + R[M,N]                (MODE 2)
#define GBM 128
#define GBN 128
#define GBK 32
#define LDA_S 40
#define LDB_S 136
#define SA_STAGE (GBM * LDA_S)          // 5120 floats
#define SB_STAGE (GBK * LDB_S)          // 4352 floats
#define GEMM_SMEM_BYTES ((2 * SA_STAGE + 2 * SB_STAGE) * 4)   // 75776

template <int MODE>
__global__ __launch_bounds__(256) void gemm_tc(
        const float* __restrict__ A, const float* __restrict__ B,
        const float* __restrict__ bias, const float* __restrict__ R,
        float* __restrict__ C, int M, int N, int K) {
    extern __shared__ float smem[];
    float* sAbuf[2] = { smem, smem + SA_STAGE };
    float* sBbuf[2] = { smem + 2 * SA_STAGE, smem + 2 * SA_STAGE + SB_STAGE };

    int tid = threadIdx.x;           // 256
    int wid = tid >> 5, lane = tid & 31;
    int warp_m = wid >> 2;           // 0..1
    int warp_n = wid & 3;            // 0..3
    int row0 = blockIdx.y * GBM, col0 = blockIdx.x * GBN;

    wmma::fragment<wmma::accumulator, 16, 16, 8, float> acc[4][2];
    #pragma unroll
    for (int i = 0; i < 4; i++)
        #pragma unroll
        for (int j = 0; j < 2; j++)
            wmma::fill_fragment(acc[i][j], 0.0f);

    // per-thread load coordinates (4 x 16B for A, 4 x 16B for B per stage)
    int am[4], ak[4], bk[4], bn[4];
    #pragma unroll
    for (int i = 0; i < 4; i++) {
        int idx = tid + i * 256;
        am[i] = idx >> 3;  ak[i] = (idx & 7) * 4;
        bk[i] = idx >> 5;  bn[i] = (idx & 31) * 4;
    }

    // prologue: stage 0
    #pragma unroll
    for (int i = 0; i < 4; i++) {
        cp16(&sAbuf[0][am[i] * LDA_S + ak[i]], A + (size_t)(row0 + am[i]) * K + ak[i]);
        cp16(&sBbuf[0][bk[i] * LDB_S + bn[i]], B + (size_t)bk[i] * N + col0 + bn[i]);
    }
    cp_commit();

    int KT = K / GBK;
    for (int kt = 0; kt < KT; kt++) {
        int cur = kt & 1;
        if (kt + 1 < KT) {
            int nxt = cur ^ 1;
            int k0 = (kt + 1) * GBK;
            #pragma unroll
            for (int i = 0; i < 4; i++) {
                cp16(&sAbuf[nxt][am[i] * LDA_S + ak[i]],
                     A + (size_t)(row0 + am[i]) * K + k0 + ak[i]);
                cp16(&sBbuf[nxt][bk[i] * LDB_S + bn[i]],
                     B + (size_t)(k0 + bk[i]) * N + col0 + bn[i]);
            }
            cp_commit();
            cp_wait<1>();
        } else {
            cp_wait<0>();
        }
        __syncthreads();

        float* sA = sAbuf[cur];
        float* sB = sBbuf[cur];
        #pragma unroll
        for (int ks = 0; ks < GBK; ks += 8) {
            wmma::fragment<wmma::matrix_a, 16, 16, 8, wmma::precision::tf32, wmma::row_major> af[4];
            wmma::fragment<wmma::matrix_b, 16, 16, 8, wmma::precision::tf32, wmma::row_major> bf[2];
            #pragma unroll
            for (int i = 0; i < 4; i++)
                wmma::load_matrix_sync(af[i], &sA[(warp_m * 64 + i * 16) * LDA_S + ks], LDA_S);
            #pragma unroll
            for (int j = 0; j < 2; j++)
                wmma::load_matrix_sync(bf[j], &sB[ks * LDB_S + warp_n * 32 + j * 16], LDB_S);
            #pragma unroll
            for (int i = 0; i < 4; i++)
                #pragma unroll
                for (int j = 0; j < 2; j++)
                    wmma::mma_sync(acc[i][j], af[i], bf[j], acc[i][j]);
        }
        __syncthreads();
    }

    // epilogue: stage each 16x16 frag through per-warp smem patch
    float* stage = &smem[wid * 272];
    int r = lane >> 1, c0 = (lane & 1) * 8;
    #pragma unroll
    for (int i = 0; i < 4; i++) {
        #pragma unroll
        for (int j = 0; j < 2; j++) {
            __syncwarp();
            wmma::store_matrix_sync(stage, acc[i][j], 16, wmma::mem_row_major);
            __syncwarp();
            int m = row0 + warp_m * 64 + i * 16 + r;
            int n = col0 + warp_n * 32 + j * 16 + c0;
            float bb[8];
            *(float4*)(bb)     = *(const float4*)(bias + n);
            *(float4*)(bb + 4) = *(const float4*)(bias + n + 4);
            float out[8];
            #pragma unroll
            for (int t = 0; t < 8; t++) out[t] = stage[r * 16 + c0 + t] + bb[t];
            if (MODE == 1) {
                #pragma unroll
                for (int t = 0; t < 8; t++)
                    out[t] = wmma::__float_to_tf32(gelu_tanh(out[t]));
            }
            if (MODE == 2) {
                float rr[8];
                *(float4*)(rr)     = *(const float4*)(R + (size_t)m * N + n);
                *(float4*)(rr + 4) = *(const float4*)(R + (size_t)m * N + n + 4);
                #pragma unroll
                for (int t = 0; t < 8; t++) out[t] += rr[t];
            }
            *(float4*)(C + (size_t)m * N + n)     = *(float4*)(out);
            *(float4*)(C + (size_t)m * N + n + 4) = *(float4*)(out + 4);
        }
    }
}

// ---------------- attention: QK^T (tensor core, smem-staged) ----------------
#define LDT 72
__global__ __launch_bounds__(128) void qk_kernel(
        const float* __restrict__ q, const float* __restrict__ k,
        float* __restrict__ att) {
    __shared__ float sQ[64 * LDT];
    __shared__ float sK[64 * LDT];
    int mt = blockIdx.x;          // query tile 0..8
    int nt = blockIdx.y;          // key tile 0..8
    int nh = blockIdx.z;          // n*NH+h
    int n = nh / NH, h = nh % NH;
    const float* qb = q + ((size_t)n * L * NH + h) * HD;  // row stride 768
    const float* kb = k + ((size_t)n * L * NH + h) * HD;
    float* sb = att + (size_t)nh * L * L;

    int tid = threadIdx.x;        // 128
    #pragma unroll
    for (int i = 0; i < 8; i++) {
        int idx = tid + i * 128;
        int row = idx >> 4, c4 = (idx & 15) * 4;
        float4 tq = *(const float4*)(qb + (size_t)(mt * 64 + row) * (NH * HD) + c4);
        float4 tk = *(const float4*)(kb + (size_t)(nt * 64 + row) * (NH * HD) + c4);
        float* dq = &sQ[row * LDT + c4];
        dq[0] = wmma::__float_to_tf32(tq.x); dq[1] = wmma::__float_to_tf32(tq.y);
        dq[2] = wmma::__float_to_tf32(tq.z); dq[3] = wmma::__float_to_tf32(tq.w);
        float* dk = &sK[row * LDT + c4];
        dk[0] = wmma::__float_to_tf32(tk.x); dk[1] = wmma::__float_to_tf32(tk.y);
        dk[2] = wmma::__float_to_tf32(tk.z); dk[3] = wmma::__float_to_tf32(tk.w);
    }
    __syncthreads();

    int wid = tid >> 5;           // 4 warps: 2x2, each 32x32
    int wm = wid >> 1, wn = wid & 1;

    wmma::fragment<wmma::accumulator, 16, 16, 8, float> acc[2][2];
    #pragma unroll
    for (int i = 0; i < 2; i++)
        #pragma unroll
        for (int j = 0; j < 2; j++) wmma::fill_fragment(acc[i][j], 0.0f);

    #pragma unroll
    for (int k0 = 0; k0 < HD; k0 += 8) {
        wmma::fragment<wmma::matrix_a, 16, 16, 8, wmma::precision::tf32, wmma::row_major> af[2];
        wmma::fragment<wmma::matrix_b, 16, 16, 8, wmma::precision::tf32, wmma::col_major> bf[2];
        #pragma unroll
        for (int i = 0; i < 2; i++)
            wmma::load_matrix_sync(af[i], &sQ[(wm * 32 + i * 16) * LDT + k0], LDT);
        #pragma unroll
        for (int j = 0; j < 2; j++)
            wmma::load_matrix_sync(bf[j], &sK[(wn * 32 + j * 16) * LDT + k0], LDT);
        #pragma unroll
        for (int i = 0; i < 2; i++)
            #pragma unroll
            for (int j = 0; j < 2; j++)
                wmma::mma_sync(acc[i][j], af[i], bf[j], acc[i][j]);
    }
    int row0 = mt * 64 + wm * 32;
    int col0 = nt * 64 + wn * 32;
    #pragma unroll
    for (int i = 0; i < 2; i++)
        #pragma unroll
        for (int j = 0; j < 2; j++)
            wmma::store_matrix_sync(sb + (size_t)(row0 + i * 16) * L + col0 + j * 16,
                                    acc[i][j], L, wmma::mem_row_major);
}

// ---------------- softmax over rows of scores (scale folded) ----------------
__global__ void softmax_kernel(float* __restrict__ att) {
    int lane = threadIdx.x & 31;
    int gw = (blockIdx.x * 256 + threadIdx.x) >> 5;   // row id 0 .. NB*NH*L-1
    float* row = att + (size_t)gw * L;
    float r[18];
    float m = -1e30f;
    #pragma unroll
    for (int i = 0; i < 18; i++) { r[i] = row[lane + 32 * i]; m = fmaxf(m, r[i]); }
    #pragma unroll
    for (int o = 16; o > 0; o >>= 1) m = fmaxf(m, __shfl_xor_sync(0xffffffffu, m, o));
    float s = 0.f;
    #pragma unroll
    for (int i = 0; i < 18; i++) { r[i] = __expf(0.125f * (r[i] - m)); s += r[i]; }
    #pragma unroll
    for (int o = 16; o > 0; o >>= 1) s += __shfl_xor_sync(0xffffffffu, s, o);
    float inv = 1.0f / s;
    #pragma unroll
    for (int i = 0; i < 18; i++) row[lane + 32 * i] = r[i] * inv;
}

// ---------------- attention: probs @ V (tensor core, smem-staged) -----------
// output o is a GEMM A operand -> tf32-round the accumulators before store.
__global__ __launch_bounds__(128) void av_kernel(
        const float* __restrict__ att, const float* __restrict__ v,
        float* __restrict__ o) {
    __shared__ float sP[64 * LDT];
    __shared__ float sV[64 * LDT];
    int mt = blockIdx.x;          // query tile 0..8
    int nh = blockIdx.y;
    int n = nh / NH, h = nh % NH;
    const float* sb = att + (size_t)nh * L * L;
    const float* vb = v + ((size_t)n * L * NH + h) * HD;
    float* ob = o + ((size_t)n * L * NH + h) * HD;

    int tid = threadIdx.x;        // 128
    int wid = tid >> 5;
    int wm = wid >> 1, wn = wid & 1;

    wmma::fragment<wmma::accumulator, 16, 16, 8, float> acc[2][2];
    #pragma unroll
    for (int i = 0; i < 2; i++)
        #pragma unroll
        for (int j = 0; j < 2; j++) wmma::fill_fragment(acc[i][j], 0.0f);

    for (int kt = 0; kt < L / 64; kt++) {
        #pragma unroll
        for (int i = 0; i < 8; i++) {
            int idx = tid + i * 128;
            int row = idx >> 4, c4 = (idx & 15) * 4;
            float4 tp = *(const float4*)(sb + (size_t)(mt * 64 + row) * L + kt * 64 + c4);
            float4 tv = *(const float4*)(vb + (size_t)(kt * 64 + row) * (NH * HD) + c4);
            float* dp = &sP[row * LDT + c4];
            dp[0] = wmma::__float_to_tf32(tp.x); dp[1] = wmma::__float_to_tf32(tp.y);
            dp[2] = wmma::__float_to_tf32(tp.z); dp[3] = wmma::__float_to_tf32(tp.w);
            float* dv = &sV[row * LDT + c4];
            dv[0] = wmma::__float_to_tf32(tv.x); dv[1] = wmma::__float_to_tf32(tv.y);
            dv[2] = wmma::__float_to_tf32(tv.z); dv[3] = wmma::__float_to_tf32(tv.w);
        }
        __syncthreads();
        #pragma unroll
        for (int k0 = 0; k0 < 64; k0 += 8) {
            wmma::fragment<wmma::matrix_a, 16, 16, 8, wmma::precision::tf32, wmma::row_major> af[2];
            wmma::fragment<wmma::matrix_b, 16, 16, 8, wmma::precision::tf32, wmma::row_major> bf[2];
            #pragma unroll
            for (int i = 0; i < 2; i++)
                wmma::load_matrix_sync(af[i], &sP[(wm * 32 + i * 16) * LDT + k0], LDT);
            #pragma unroll
            for (int j = 0; j < 2; j++)
                wmma::load_matrix_sync(bf[j], &sV[k0 * LDT + wn * 32 + j * 16], LDT);
            #pragma unroll
            for (int i = 0; i < 2; i++)
                #pragma unroll
                for (int j = 0; j < 2; j++)
                    wmma::mma_sync(acc[i][j], af[i], bf[j], acc[i][j]);
        }
        __syncthreads();
    }
    int row0 = mt * 64 + wm * 32;
    int col0 = wn * 32;
    #pragma unroll
    for (int i = 0; i < 2; i++)
        #pragma unroll
        for (int j = 0; j < 2; j++) {
            #pragma unroll
            for (int t = 0; t < acc[i][j].num_elements; t++)
                acc[i][j].x[t] = wmma::__float_to_tf32(acc[i][j].x[t]);
            wmma::store_matrix_sync(ob + (size_t)(row0 + i * 16) * (NH * HD) + col0 + j * 16,
                                    acc[i][j], NH * HD, wmma::mem_row_major);
        }
}

// ---------------- final mean over tokens ----------------
__global__ void mean_kernel(const float* __restrict__ y, float* __restrict__ out) {
    int n = blockIdx.x;
    int c = threadIdx.x;   // 768
    float s = 0.f;
    for (int l = 0; l < L; l++) s += y[((size_t)n * L + l) * W + c];
    out[n * W + c] = s * (1.0f / (float)L);
}

// ---------------- host orchestration ----------------
extern "C" void kernel_launch(void* const* d_in, const int* in_sizes, int n_in,
                              void* d_out, int out_size) {
    const float* image   = (const float*)d_in[0];
    const float* ckern   = (const float*)d_in[1];
    const float* cbias   = (const float*)d_in[2];
    const float* ln1s    = (const float*)d_in[3];
    const float* ln1b    = (const float*)d_in[4];
    const float* wq      = (const float*)d_in[5];
    const float* bq      = (const float*)d_in[6];
    const float* wk      = (const float*)d_in[7];
    const float* bk      = (const float*)d_in[8];
    const float* wv      = (const float*)d_in[9];
    const float* bv      = (const float*)d_in[10];
    const float* wo      = (const float*)d_in[11];
    const float* bo      = (const float*)d_in[12];
    const float* ln2s    = (const float*)d_in[13];
    const float* ln2b    = (const float*)d_in[14];
    const float* w1      = (const float*)d_in[15];
    const float* b1      = (const float*)d_in[16];
    const float* w2      = (const float*)d_in[17];
    const float* b2      = (const float*)d_in[18];
    const float* lnfs    = (const float*)d_in[19];
    const float* lnfb    = (const float*)d_in[20];
    float* out = (float*)d_out;

    float *x, *y, *q, *k, *v, *o, *hbuf, *att, *wt;
    cudaGetSymbolAddress((void**)&x, g_x);
    cudaGetSymbolAddress((void**)&y, g_y);
    cudaGetSymbolAddress((void**)&q, g_q);
    cudaGetSymbolAddress((void**)&k, g_k);
    cudaGetSymbolAddress((void**)&v, g_v);
    cudaGetSymbolAddress((void**)&o, g_o);
    cudaGetSymbolAddress((void**)&hbuf, g_h);
    cudaGetSymbolAddress((void**)&att, g_att);
    cudaGetSymbolAddress((void**)&wt, g_wt);

    // opt-in to >48KB dynamic smem for the GEMM kernels
    cudaFuncSetAttribute(gemm_tc<0>, cudaFuncAttributeMaxDynamicSharedMemorySize, GEMM_SMEM_BYTES);
    cudaFuncSetAttribute(gemm_tc<1>, cudaFuncAttributeMaxDynamicSharedMemorySize, GEMM_SMEM_BYTES);
    cudaFuncSetAttribute(gemm_tc<2>, cudaFuncAttributeMaxDynamicSharedMemorySize, GEMM_SMEM_BYTES);

    const size_t WW = (size_t)W * W;
    const size_t WM = (size_t)W * MLP;

    // tf32-rounded weight pointers inside g_wt
    float* cwt  = wt;                                  // conv kernel
    auto lw = [&](int l, int which) -> float* {        // which: 0..3 = q,k,v,o; 4 = w1; 5 = w2
        float* base = wt + CONV_SZ + (size_t)l * LAYER_SZ;
        if (which < 4) return base + (size_t)which * WQKV_SZ;
        if (which == 4) return base + 4 * (size_t)WQKV_SZ;
        return base + 4 * (size_t)WQKV_SZ + W1_SZ;
    };

    // build conversion job list
    CvtJobs jobs;
    jobs.j[0] = { ckern, cwt, CONV_SZ / 4 };
    for (int l = 0; l < DPT; l++) {
        jobs.j[1 + l * 6 + 0] = { wq + l * WW, lw(l, 0), WQKV_SZ / 4 };
        jobs.j[1 + l * 6 + 1] = { wk + l * WW, lw(l, 1), WQKV_SZ / 4 };
        jobs.j[1 + l * 6 + 2] = { wv + l * WW, lw(l, 2), WQKV_SZ / 4 };
        jobs.j[1 + l * 6 + 3] = { wo + l * WW, lw(l, 3), WQKV_SZ / 4 };
        jobs.j[1 + l * 6 + 4] = { w1 + l * WM, lw(l, 4), W1_SZ / 4 };
        jobs.j[1 + l * 6 + 5] = { w2 + l * WM, lw(l, 5), W1_SZ / 4 };
    }
    cvt_weights_kernel<<<dim3(256, 25), 256>>>(jobs);

    // patch embed: im2col (tf32-rounded) + GEMM
    {
        int total = M_ROWS * W;
        im2col_kernel<<<(total + 255) / 256, 256>>>(image, y);
        dim3 gg(W / GBN, M_ROWS / GBM);
        gemm_tc<0><<<gg, 256, GEMM_SMEM_BYTES>>>(y, cwt, cbias, nullptr, x, M_ROWS, W, W);
    }
    rope_cache_kernel<<<(L * 16 + 255) / 256, 256>>>();

    dim3 gw(W / GBN, M_ROWS / GBM);       // 768-wide GEMMs: (6, 36)
    dim3 gm(MLP / GBN, M_ROWS / GBM);     // 3072-wide GEMM:  (24, 36)
    int rope_total = NB * L * NH * 32;
    dim3 gqk(L / 64, L / 64, NB * NH);    // (9, 9, 96)
    dim3 gav(L / 64, NB * NH);            // (9, 96)
    int smx_blocks = (NB * NH * L) / 8;   // 6912

    for (int l = 0; l < DPT; l++) {
        ln_warp<<<M_ROWS / 8, 256>>>(x, ln1s + l * W, ln1b + l * W, y, 1);
        gemm_tc<0><<<gw, 256, GEMM_SMEM_BYTES>>>(y, lw(l, 0), bq + l * W, nullptr, q, M_ROWS, W, W);
        gemm_tc<0><<<gw, 256, GEMM_SMEM_BYTES>>>(y, lw(l, 1), bk + l * W, nullptr, k, M_ROWS, W, W);
        gemm_tc<0><<<gw, 256, GEMM_SMEM_BYTES>>>(y, lw(l, 2), bv + l * W, nullptr, v, M_ROWS, W, W);
        rope_apply_kernel<<<(rope_total + 255) / 256, 256>>>(q);
        rope_apply_kernel<<<(rope_total + 255) / 256, 256>>>(k);
        qk_kernel<<<gqk, 128>>>(q, k, att);
        softmax_kernel<<<smx_blocks, 256>>>(att);
        av_kernel<<<gav, 128>>>(att, v, o);
        // x = x + (o @ wo + bo)
        gemm_tc<2><<<gw, 256, GEMM_SMEM_BYTES>>>(o, lw(l, 3), bo + l * W, x, x, M_ROWS, W, W);
        ln_warp<<<M_ROWS / 8, 256>>>(x, ln2s + l * W, ln2b + l * W, y, 1);
        gemm_tc<1><<<gm, 256, GEMM_SMEM_BYTES>>>(y, lw(l, 4), b1 + l * MLP, nullptr, hbuf, M_ROWS, MLP, W);
        gemm_tc<2><<<gw, 256, GEMM_SMEM_BYTES>>>(hbuf, lw(l, 5), b2 + l * W, x, x, M_ROWS, W, MLP);
    }

    ln_warp<<<M_ROWS / 8, 256>>>(x, lnfs, lnfb, y, 0);
    mean_kernel<<<NB, W>>>(y, out);
}

// round 12
// speedup vs baseline: 3.9988x; 3.9988x over previous
#include <cuda_runtime.h>
#include <cuda_fp16.h>
#include <cuda_bf16.h>
#include <mma.h>
#include <cstdint>

using namespace nvcuda;

// ---------------- problem constants ----------------
#define NB 8            // batch
#define HW 384
#define CIN 3
#define PATCH 16
#define GRID 24         // 384/16
#define L 576           // GRID*GRID tokens
#define W 768           // width
#define DPT 4           // depth
#define NH 12           // heads
#define HD 64           // head dim
#define MLP 3072
#define M_ROWS (NB*L)   // 4608

// ---------------- scratch (device globals; no allocation allowed) ----------
__device__ float g_x[M_ROWS * W];     // residual stream
__device__ float g_y[M_ROWS * W];     // LN output / im2col buffer
__device__ float g_q[M_ROWS * W];
__device__ float g_k[M_ROWS * W];
__device__ float g_v[M_ROWS * W];
__device__ float g_o[M_ROWS * W];
__device__ float g_h[M_ROWS * MLP];   // MLP hidden
__device__ float g_att[(size_t)NB * NH * L * L];  // attention scores/probs
__device__ float g_rope[4][L][16];    // cosx,sinx,cosy,siny

// ---------------- helpers ----------------
__device__ __forceinline__ float gelu_tanh(float x) {
    const float k0 = 0.7978845608028654f;   // sqrt(2/pi)
    float x3 = x * x * x;
    return 0.5f * x * (1.0f + tanhf(k0 * (x + 0.044715f * x3)));
}

// store 4 floats as 4 fp16 (RN) at an 8B-aligned smem address
__device__ __forceinline__ void st_half4(__half* d, float4 t) {
    *(__half2*)(d)     = __floats2half2_rn(t.x, t.y);
    *(__half2*)(d + 2) = __floats2half2_rn(t.z, t.w);
}

// ---------------- im2col: image(NHWC) -> rows [NB*L, 768] -------------------
__global__ void im2col_kernel(const float* __restrict__ img, float* __restrict__ out) {
    int idx = blockIdx.x * blockDim.x + threadIdx.x;
    const int total = M_ROWS * W;
    if (idx >= total) return;
    int col = idx % W;
    int rest = idx / W;
    int p = rest % L;
    int n = rest / L;
    int c = col % CIN;
    int ij = col / CIN;
    int j = ij % PATCH;
    int i = ij / PATCH;
    int px = p % GRID, py = p / GRID;
    out[idx] = img[(((size_t)n * HW + (py * PATCH + i)) * HW + (px * PATCH + j)) * CIN + c];
}

// ---------------- RoPE cache ----------------
__global__ void rope_cache_kernel() {
    int idx = blockIdx.x * blockDim.x + threadIdx.x;
    if (idx >= L * 16) return;
    int l = idx / 16, f = idx % 16;
    int px = l % GRID, py = l / GRID;
    float u = (px + 0.5f) / (float)GRID;
    float v = (py + 0.5f) / (float)GRID;
    float fr = (float)f / (15.0f + 1e-9f);
    float inv = expf(-fr * 9.210340371976184f);  // 10000^-fr
    float ax = u * inv, ay = v * inv;
    g_rope[0][l][f] = cosf(ax);
    g_rope[1][l][f] = sinf(ax);
    g_rope[2][l][f] = cosf(ay);
    g_rope[3][l][f] = sinf(ay);
}

// ---------------- RoPE apply (in place on q or k) ----------------
__global__ void rope_apply_kernel(float* __restrict__ t) {
    int idx = blockIdx.x * blockDim.x + threadIdx.x;
    const int total = NB * L * NH * 32;   // 32 pairs per head
    if (idx >= total) return;
    int pair = idx & 31;
    int rest = idx >> 5;
    int h = rest % NH; rest /= NH;
    int l = rest % L;
    int n = rest / L;
    int f = pair & 15;
    float c, s;
    if (pair < 16) { c = g_rope[0][l][f]; s = g_rope[1][l][f]; }
    else           { c = g_rope[2][l][f]; s = g_rope[3][l][f]; }
    size_t base = ((((size_t)n * L + l) * NH + h) * HD) + pair * 2;
    float x = t[base], y = t[base + 1];
    t[base]     = x * c - y * s;
    t[base + 1] = x * s + y * c;
}

// ---------------- LayerNorm: warp per row, C = 768 fixed ----------------
__global__ void ln_warp(const float* __restrict__ x, const float* __restrict__ sc,
                        const float* __restrict__ bi, float* __restrict__ y) {
    int wid = threadIdx.x >> 5, lane = threadIdx.x & 31;
    int row = blockIdx.x * 8 + wid;
    const float4* xr = (const float4*)(x + (size_t)row * W);
    float4 v[6];
    float s1 = 0.f, s2 = 0.f;
    #pragma unroll
    for (int i = 0; i < 6; i++) {
        v[i] = xr[lane + 32 * i];
        s1 += v[i].x + v[i].y + v[i].z + v[i].w;
        s2 += v[i].x * v[i].x + v[i].y * v[i].y + v[i].z * v[i].z + v[i].w * v[i].w;
    }
    #pragma unroll
    for (int o = 16; o > 0; o >>= 1) {
        s1 += __shfl_xor_sync(0xffffffffu, s1, o);
        s2 += __shfl_xor_sync(0xffffffffu, s2, o);
    }
    float mean = s1 * (1.0f / W);
    float var  = s2 * (1.0f / W) - mean * mean;
    float rstd = rsqrtf(var + 1e-6f);
    float4* yr = (float4*)(y + (size_t)row * W);
    const float4* s4 = (const float4*)sc;
    const float4* b4 = (const float4*)bi;
    #pragma unroll
    for (int i = 0; i < 6; i++) {
        int idx = lane + 32 * i;
        float4 sv = s4[idx], bv = b4[idx], o;
        o.x = (v[i].x - mean) * rstd * sv.x + bv.x;
        o.y = (v[i].y - mean) * rstd * sv.y + bv.y;
        o.z = (v[i].z - mean) * rstd * sv.z + bv.z;
        o.w = (v[i].w - mean) * rstd * sv.w + bv.w;
        yr[idx] = o;
    }
}

// ---------------- tensor-core fp16 GEMM (fp32 accum), reg double-buffer -----
// C[M,N] = A[M,K] @ B[K,N] + bias[N]   (MODE 0)
//          gelu(...)                   (MODE 1)
//          ... + R[M,N]                (MODE 2)
// fp16 mantissa == tf32 mantissa (10 bits): same rounding error as the tf32
// path, but the full-rate legacy HMMA pipe + half-size smem tiles.
#define GBM 128
#define GBN 128
#define GBK 32
#define LDA_S 40    // halves; 80B row stride (16B-multiple)
#define LDB_S 136   // halves; 272B row stride

template <int MODE>
__global__ __launch_bounds__(256) void gemm_tc(
        const float* __restrict__ A, const float* __restrict__ B,
        const float* __restrict__ bias, const float* __restrict__ R,
        float* __restrict__ C, int M, int N, int K) {
    __shared__ __align__(16) __half sA[GBM * LDA_S];   // 10240 B
    __shared__ __align__(16) __half sB[GBK * LDB_S];   //  8704 B

    int tid = threadIdx.x;           // 256
    int wid = tid >> 5, lane = tid & 31;
    int warp_m = wid >> 2;           // 0..1
    int warp_n = wid & 3;            // 0..3
    int row0 = blockIdx.y * GBM, col0 = blockIdx.x * GBN;

    wmma::fragment<wmma::accumulator, 16, 16, 16, float> acc[4][2];
    #pragma unroll
    for (int i = 0; i < 4; i++)
        #pragma unroll
        for (int j = 0; j < 2; j++)
            wmma::fill_fragment(acc[i][j], 0.0f);

    float4 pa[4], pb[4];
    // prologue: load k-tile 0 into registers
    #pragma unroll
    for (int i = 0; i < 4; i++) {
        int idx = tid + i * 256;
        pa[i] = *(const float4*)(A + (size_t)(row0 + (idx >> 3)) * K + ((idx & 7) * 4));
        pb[i] = *(const float4*)(B + (size_t)(idx >> 5) * N + col0 + ((idx & 31) * 4));
    }
    #pragma unroll
    for (int i = 0; i < 4; i++) {
        int idx = tid + i * 256;
        st_half4(&sA[(idx >> 3) * LDA_S + (idx & 7) * 4], pa[i]);
        st_half4(&sB[(idx >> 5) * LDB_S + (idx & 31) * 4], pb[i]);
    }
    __syncthreads();

    int KT = K / GBK;
    for (int kt = 0; kt < KT; kt++) {
        // prefetch next k-tile into registers (overlaps with compute below)
        if (kt + 1 < KT) {
            int k0 = (kt + 1) * GBK;
            #pragma unroll
            for (int i = 0; i < 4; i++) {
                int idx = tid + i * 256;
                pa[i] = *(const float4*)(A + (size_t)(row0 + (idx >> 3)) * K + k0 + ((idx & 7) * 4));
                pb[i] = *(const float4*)(B + (size_t)(k0 + (idx >> 5)) * N + col0 + ((idx & 31) * 4));
            }
        }
        // compute current smem tile (2 ksteps of 16)
        #pragma unroll
        for (int ks = 0; ks < 2; ks++) {
            wmma::fragment<wmma::matrix_a, 16, 16, 16, __half, wmma::row_major> af[4];
            wmma::fragment<wmma::matrix_b, 16, 16, 16, __half, wmma::row_major> bf[2];
            #pragma unroll
            for (int i = 0; i < 4; i++)
                wmma::load_matrix_sync(af[i], &sA[(warp_m * 64 + i * 16) * LDA_S + ks * 16], LDA_S);
            #pragma unroll
            for (int j = 0; j < 2; j++)
                wmma::load_matrix_sync(bf[j], &sB[(ks * 16) * LDB_S + warp_n * 32 + j * 16], LDB_S);
            #pragma unroll
            for (int i = 0; i < 4; i++)
                #pragma unroll
                for (int j = 0; j < 2; j++)
                    wmma::mma_sync(acc[i][j], af[i], bf[j], acc[i][j]);
        }
        __syncthreads();
        if (kt + 1 < KT) {
            #pragma unroll
            for (int i = 0; i < 4; i++) {
                int idx = tid + i * 256;
                st_half4(&sA[(idx >> 3) * LDA_S + (idx & 7) * 4], pa[i]);
                st_half4(&sB[(idx >> 5) * LDB_S + (idx & 31) * 4], pb[i]);
            }
            __syncthreads();
        }
    }

    // epilogue: stage each 16x16 frag through per-warp smem patch (alias sA)
    float* stage = reinterpret_cast<float*>(sA) + wid * 272;
    int r = lane >> 1, c0 = (lane & 1) * 8;
    #pragma unroll
    for (int i = 0; i < 4; i++) {
        #pragma unroll
        for (int j = 0; j < 2; j++) {
            __syncwarp();
            wmma::store_matrix_sync(stage, acc[i][j], 16, wmma::mem_row_major);
            __syncwarp();
            int m = row0 + warp_m * 64 + i * 16 + r;
            int n = col0 + warp_n * 32 + j * 16 + c0;
            float bb[8];
            *(float4*)(bb)     = *(const float4*)(bias + n);
            *(float4*)(bb + 4) = *(const float4*)(bias + n + 4);
            float out[8];
            #pragma unroll
            for (int t = 0; t < 8; t++) out[t] = stage[r * 16 + c0 + t] + bb[t];
            if (MODE == 1) {
                #pragma unroll
                for (int t = 0; t < 8; t++) out[t] = gelu_tanh(out[t]);
            }
            if (MODE == 2) {
                float rr[8];
                *(float4*)(rr)     = *(const float4*)(R + (size_t)m * N + n);
                *(float4*)(rr + 4) = *(const float4*)(R + (size_t)m * N + n + 4);
                #pragma unroll
                for (int t = 0; t < 8; t++) out[t] += rr[t];
            }
            *(float4*)(C + (size_t)m * N + n)     = *(float4*)(out);
            *(float4*)(C + (size_t)m * N + n + 4) = *(float4*)(out + 4);
        }
    }
}

// ---------------- attention: QK^T (fp16 tensor core, smem-staged) -----------
// scores[nh][q][k] = sum_d Q[q][d]*K[k][d]  (scale folded into softmax)
#define LDT 72   // halves; 144B row stride
__global__ __launch_bounds__(128) void qk_kernel(
        const float* __restrict__ q, const float* __restrict__ k,
        float* __restrict__ att) {
    __shared__ __align__(16) __half sQ[64 * LDT];
    __shared__ __align__(16) __half sK[64 * LDT];
    int mt = blockIdx.x;          // query tile 0..8
    int nt = blockIdx.y;          // key tile 0..8
    int nh = blockIdx.z;          // n*NH+h
    int n = nh / NH, h = nh % NH;
    const float* qb = q + ((size_t)n * L * NH + h) * HD;  // row stride 768
    const float* kb = k + ((size_t)n * L * NH + h) * HD;
    float* sb = att + (size_t)nh * L * L;

    int tid = threadIdx.x;        // 128
    #pragma unroll
    for (int i = 0; i < 8; i++) {
        int idx = tid + i * 128;
        int row = idx >> 4, c4 = (idx & 15) * 4;
        float4 tq = *(const float4*)(qb + (size_t)(mt * 64 + row) * (NH * HD) + c4);
        float4 tk = *(const float4*)(kb + (size_t)(nt * 64 + row) * (NH * HD) + c4);
        st_half4(&sQ[row * LDT + c4], tq);
        st_half4(&sK[row * LDT + c4], tk);
    }
    __syncthreads();

    int wid = tid >> 5;           // 4 warps: 2x2, each 32x32
    int wm = wid >> 1, wn = wid & 1;

    wmma::fragment<wmma::accumulator, 16, 16, 16, float> acc[2][2];
    #pragma unroll
    for (int i = 0; i < 2; i++)
        #pragma unroll
        for (int j = 0; j < 2; j++) wmma::fill_fragment(acc[i][j], 0.0f);

    #pragma unroll
    for (int k0 = 0; k0 < HD; k0 += 16) {
        wmma::fragment<wmma::matrix_a, 16, 16, 16, __half, wmma::row_major> af[2];
        wmma::fragment<wmma::matrix_b, 16, 16, 16, __half, wmma::col_major> bf[2];
        #pragma unroll
        for (int i = 0; i < 2; i++)
            wmma::load_matrix_sync(af[i], &sQ[(wm * 32 + i * 16) * LDT + k0], LDT);
        #pragma unroll
        for (int j = 0; j < 2; j++)
            wmma::load_matrix_sync(bf[j], &sK[(wn * 32 + j * 16) * LDT + k0], LDT);
        #pragma unroll
        for (int i = 0; i < 2; i++)
            #pragma unroll
            for (int j = 0; j < 2; j++)
                wmma::mma_sync(acc[i][j], af[i], bf[j], acc[i][j]);
    }
    int row0 = mt * 64 + wm * 32;
    int col0 = nt * 64 + wn * 32;
    #pragma unroll
    for (int i = 0; i < 2; i++)
        #pragma unroll
        for (int j = 0; j < 2; j++)
            wmma::store_matrix_sync(sb + (size_t)(row0 + i * 16) * L + col0 + j * 16,
                                    acc[i][j], L, wmma::mem_row_major);
}

// ---------------- softmax over rows of scores (scale folded) ----------------
__global__ void softmax_kernel(float* __restrict__ att) {
    int lane = threadIdx.x & 31;
    int gw = (blockIdx.x * 256 + threadIdx.x) >> 5;   // row id 0 .. NB*NH*L-1
    float* row = att + (size_t)gw * L;
    float r[18];
    float m = -1e30f;
    #pragma unroll
    for (int i = 0; i < 18; i++) { r[i] = row[lane + 32 * i]; m = fmaxf(m, r[i]); }
    #pragma unroll
    for (int o = 16; o > 0; o >>= 1) m = fmaxf(m, __shfl_xor_sync(0xffffffffu, m, o));
    float s = 0.f;
    #pragma unroll
    for (int i = 0; i < 18; i++) { r[i] = __expf(0.125f * (r[i] - m)); s += r[i]; }
    #pragma unroll
    for (int o = 16; o > 0; o >>= 1) s += __shfl_xor_sync(0xffffffffu, s, o);
    float inv = 1.0f / s;
    #pragma unroll
    for (int i = 0; i < 18; i++) row[lane + 32 * i] = r[i] * inv;
}

// ---------------- attention: probs @ V (fp16 tensor core, smem-staged) ------
__global__ __launch_bounds__(128) void av_kernel(
        const float* __restrict__ att, const float* __restrict__ v,
        float* __restrict__ o) {
    __shared__ __align__(16) __half sP[64 * LDT];
    __shared__ __align__(16) __half sV[64 * LDT];
    int mt = blockIdx.x;          // query tile 0..8
    int nh = blockIdx.y;
    int n = nh / NH, h = nh % NH;
    const float* sb = att + (size_t)nh * L * L;
    const float* vb = v + ((size_t)n * L * NH + h) * HD;
    float* ob = o + ((size_t)n * L * NH + h) * HD;

    int tid = threadIdx.x;        // 128
    int wid = tid >> 5;
    int wm = wid >> 1, wn = wid & 1;

    wmma::fragment<wmma::accumulator, 16, 16, 16, float> acc[2][2];
    #pragma unroll
    for (int i = 0; i < 2; i++)
        #pragma unroll
        for (int j = 0; j < 2; j++) wmma::fill_fragment(acc[i][j], 0.0f);

    for (int kt = 0; kt < L / 64; kt++) {
        #pragma unroll
        for (int i = 0; i < 8; i++) {
            int idx = tid + i * 128;
            int row = idx >> 4, c4 = (idx & 15) * 4;
            float4 tp = *(const float4*)(sb + (size_t)(mt * 64 + row) * L + kt * 64 + c4);
            float4 tv = *(const float4*)(vb + (size_t)(kt * 64 + row) * (NH * HD) + c4);
            st_half4(&sP[row * LDT + c4], tp);
            st_half4(&sV[row * LDT + c4], tv);
        }
        __syncthreads();
        #pragma unroll
        for (int k0 = 0; k0 < 64; k0 += 16) {
            wmma::fragment<wmma::matrix_a, 16, 16, 16, __half, wmma::row_major> af[2];
            wmma::fragment<wmma::matrix_b, 16, 16, 16, __half, wmma::row_major> bf[2];
            #pragma unroll
            for (int i = 0; i < 2; i++)
                wmma::load_matrix_sync(af[i], &sP[(wm * 32 + i * 16) * LDT + k0], LDT);
            #pragma unroll
            for (int j = 0; j < 2; j++)
                wmma::load_matrix_sync(bf[j], &sV[k0 * LDT + wn * 32 + j * 16], LDT);
            #pragma unroll
            for (int i = 0; i < 2; i++)
                #pragma unroll
                for (int j = 0; j < 2; j++)
                    wmma::mma_sync(acc[i][j], af[i], bf[j], acc[i][j]);
        }
        __syncthreads();
    }
    int row0 = mt * 64 + wm * 32;
    int col0 = wn * 32;
    #pragma unroll
    for (int i = 0; i < 2; i++)
        #pragma unroll
        for (int j = 0; j < 2; j++)
            wmma::store_matrix_sync(ob + (size_t)(row0 + i * 16) * (NH * HD) + col0 + j * 16,
                                    acc[i][j], NH * HD, wmma::mem_row_major);
}

// ---------------- final mean over tokens ----------------
__global__ void mean_kernel(const float* __restrict__ y, float* __restrict__ out) {
    int n = blockIdx.x;
    int c = threadIdx.x;   // 768
    float s = 0.f;
    for (int l = 0; l < L; l++) s += y[((size_t)n * L + l) * W + c];
    out[n * W + c] = s * (1.0f / (float)L);
}

// ---------------- host orchestration ----------------
extern "C" void kernel_launch(void* const* d_in, const int* in_sizes, int n_in,
                              void* d_out, int out_size) {
    const float* image   = (const float*)d_in[0];
    const float* ckern   = (const float*)d_in[1];
    const float* cbias   = (const float*)d_in[2];
    const float* ln1s    = (const float*)d_in[3];
    const float* ln1b    = (const float*)d_in[4];
    const float* wq      = (const float*)d_in[5];
    const float* bq      = (const float*)d_in[6];
    const float* wk      = (const float*)d_in[7];
    const float* bk      = (const float*)d_in[8];
    const float* wv      = (const float*)d_in[9];
    const float* bv      = (const float*)d_in[10];
    const float* wo      = (const float*)d_in[11];
    const float* bo      = (const float*)d_in[12];
    const float* ln2s    = (const float*)d_in[13];
    const float* ln2b    = (const float*)d_in[14];
    const float* w1      = (const float*)d_in[15];
    const float* b1      = (const float*)d_in[16];
    const float* w2      = (const float*)d_in[17];
    const float* b2      = (const float*)d_in[18];
    const float* lnfs    = (const float*)d_in[19];
    const float* lnfb    = (const float*)d_in[20];
    float* out = (float*)d_out;

    float *x, *y, *q, *k, *v, *o, *hbuf, *att;
    cudaGetSymbolAddress((void**)&x, g_x);
    cudaGetSymbolAddress((void**)&y, g_y);
    cudaGetSymbolAddress((void**)&q, g_q);
    cudaGetSymbolAddress((void**)&k, g_k);
    cudaGetSymbolAddress((void**)&v, g_v);
    cudaGetSymbolAddress((void**)&o, g_o);
    cudaGetSymbolAddress((void**)&hbuf, g_h);
    cudaGetSymbolAddress((void**)&att, g_att);

    const size_t WW = (size_t)W * W;
    const size_t WM = (size_t)W * MLP;

    // patch embed: im2col + GEMM
    {
        int total = M_ROWS * W;
        im2col_kernel<<<(total + 255) / 256, 256>>>(image, y);
        dim3 gg(W / GBN, M_ROWS / GBM);
        gemm_tc<0><<<gg, 256>>>(y, ckern, cbias, nullptr, x, M_ROWS, W, W);
    }
    rope_cache_kernel<<<(L * 16 + 255) / 256, 256>>>();

    dim3 gw(W / GBN, M_ROWS / GBM);       // 768-wide GEMMs: (6, 36)
    dim3 gm(MLP / GBN, M_ROWS / GBM);     // 3072-wide GEMM:  (24, 36)
    int rope_total = NB * L * NH * 32;
    dim3 gqk(L / 64, L / 64, NB * NH);    // (9, 9, 96)
    dim3 gav(L / 64, NB * NH);            // (9, 96)
    int smx_blocks = (NB * NH * L) / 8;   // 6912

    for (int l = 0; l < DPT; l++) {
        ln_warp<<<M_ROWS / 8, 256>>>(x, ln1s + l * W, ln1b + l * W, y);
        gemm_tc<0><<<gw, 256>>>(y, wq + l * WW, bq + l * W, nullptr, q, M_ROWS, W, W);
        gemm_tc<0><<<gw, 256>>>(y, wk + l * WW, bk + l * W, nullptr, k, M_ROWS, W, W);
        gemm_tc<0><<<gw, 256>>>(y, wv + l * WW, bv + l * W, nullptr, v, M_ROWS, W, W);
        rope_apply_kernel<<<(rope_total + 255) / 256, 256>>>(q);
        rope_apply_kernel<<<(rope_total + 255) / 256, 256>>>(k);
        qk_kernel<<<gqk, 128>>>(q, k, att);
        softmax_kernel<<<smx_blocks, 256>>>(att);
        av_kernel<<<gav, 128>>>(att, v, o);
        // x = x + (o @ wo + bo)
        gemm_tc<2><<<gw, 256>>>(o, wo + l * WW, bo + l * W, x, x, M_ROWS, W, W);
        ln_warp<<<M_ROWS / 8, 256>>>(x, ln2s + l * W, ln2b + l * W, y);
        gemm_tc<1><<<gm, 256>>>(y, w1 + l * WM, b1 + l * MLP, nullptr, hbuf, M_ROWS, MLP, W);
        gemm_tc<2><<<gw, 256>>>(hbuf, w2 + l * WM, b2 + l * W, x, x, M_ROWS, W, MLP);
    }

    ln_warp<<<M_ROWS / 8, 256>>>(x, lnfs, lnfb, y);
    mean_kernel<<<NB, W>>>(y, out);
}